// round 14
// baseline (speedup 1.0000x reference)
#include <cuda_runtime.h>
#include <cuda_bf16.h>
#include <cuda_fp16.h>
#include <math.h>
#include <float.h>
#include <stdint.h>

// ---------------- model constants ----------------
#define VCAB 50257
#define DM   768
#define NL   6
#define NH   12
#define HDIM 64
#define BBAT 4
#define TSEQ 512
#define NTOK (BBAT * TSEQ)     // 2048
#define DFF  (4 * DM)          // 3072
#define QKVW (3 * DM)          // 2304
#define NZ   (BBAT * NH)       // 48

// ---------------- scratch ----------------
__device__ float g_x[NTOK * DM];
__device__ float g_scores[(size_t)NZ * TSEQ * TSEQ];
__device__ float g_nll[NTOK];
__device__ float g_logits_scratch[(size_t)NTOK * VCAB];

// attention operands (bf16 split, unchanged precision)
__device__ __nv_bfloat16 g_qh[NZ * TSEQ * HDIM], g_ql[NZ * TSEQ * HDIM];
__device__ __nv_bfloat16 g_kh[NZ * TSEQ * HDIM], g_kl[NZ * TSEQ * HDIM];
__device__ __nv_bfloat16 g_vth[NZ * HDIM * TSEQ], g_vtl[NZ * HDIM * TSEQ];
__device__ __nv_bfloat16 g_ph[(size_t)NZ * TSEQ * TSEQ], g_pl[(size_t)NZ * TSEQ * TSEQ];

__device__ float g_bqkv[NL * QKVW];

// fp16 activations
__device__ __half g_ln16[NTOK * DM];      // LN out (attn & ff, reused sequentially)
__device__ __half g_h2_16[NTOK * DM];     // in_proj out -> qkv in
__device__ __half g_at16[NTOK * DM];      // attention out -> out_proj in
__device__ __half g_ff16[NTOK * DFF];
__device__ __half g_a16[NTOK * DM];       // LM-head in

// fp16 hi/lo weights
__device__ __half g_tin_16h[NL * DM * DM], g_tin_16l[NL * DM * DM];
__device__ __half g_tqkv_h[(size_t)NL * QKVW * DM], g_tqkv_l[(size_t)NL * QKVW * DM];
__device__ __half g_top_h[NL * DM * DM], g_top_l[NL * DM * DM];
__device__ __half g_tf1_16h[(size_t)NL * DM * DFF], g_tf1_16l[(size_t)NL * DM * DFF];
__device__ __half g_tf2_16h[(size_t)NL * DM * DFF], g_tf2_16l[(size_t)NL * DM * DFF];
__device__ __half g_tw16[(size_t)VCAB * DM];

// ---------------- helpers ----------------
static __device__ __forceinline__ uint32_t smem_u32(const void* p) {
    uint32_t a;
    asm("{ .reg .u64 t; cvta.to.shared.u64 t, %1; cvt.u32.u64 %0, t; }"
        : "=r"(a) : "l"(p));
    return a;
}
static __device__ __forceinline__ void ldsm4(uint32_t* r, uint32_t addr) {
    asm volatile("ldmatrix.sync.aligned.m8n8.x4.shared.b16 {%0,%1,%2,%3}, [%4];"
                 : "=r"(r[0]), "=r"(r[1]), "=r"(r[2]), "=r"(r[3]) : "r"(addr));
}
static __device__ __forceinline__ void mma_bf16(float* c, const uint32_t* a,
                                                const uint32_t* b) {
    asm volatile(
        "mma.sync.aligned.m16n8k16.row.col.f32.bf16.bf16.f32 "
        "{%0,%1,%2,%3}, {%4,%5,%6,%7}, {%8,%9}, {%0,%1,%2,%3};"
        : "+f"(c[0]), "+f"(c[1]), "+f"(c[2]), "+f"(c[3])
        : "r"(a[0]), "r"(a[1]), "r"(a[2]), "r"(a[3]), "r"(b[0]), "r"(b[1]));
}
static __device__ __forceinline__ void mma_f16(float* c, const uint32_t* a,
                                               const uint32_t* b) {
    asm volatile(
        "mma.sync.aligned.m16n8k16.row.col.f32.f16.f16.f32 "
        "{%0,%1,%2,%3}, {%4,%5,%6,%7}, {%8,%9}, {%0,%1,%2,%3};"
        : "+f"(c[0]), "+f"(c[1]), "+f"(c[2]), "+f"(c[3])
        : "r"(a[0]), "r"(a[1]), "r"(a[2]), "r"(a[3]), "r"(b[0]), "r"(b[1]));
}
static __device__ __forceinline__ void cpa(uint32_t dst, const void* src) {
    asm volatile("cp.async.cg.shared.global [%0], [%1], 16;" :: "r"(dst), "l"(src));
}
static __device__ __forceinline__ uint32_t sw_off(int row, int kchunk) {
    return (uint32_t)(row * 64 + ((kchunk ^ ((row >> 1) & 3)) << 4));
}
static __device__ __forceinline__ void split1(float v, __nv_bfloat16& h,
                                              __nv_bfloat16& l) {
    h = __float2bfloat16(v);
    l = __float2bfloat16(v - __bfloat162float(h));
}
static __device__ __forceinline__ void split1h(float v, __half& h, __half& l) {
    h = __float2half_rn(v);
    l = __float2half_rn(v - __half2float(h));
}

// ---------------- bf16 3-pass HMMA mainloop (attention only) ----------------
#define GBM 128
#define GBN 128
#define STG 32768
#define SM_DYN (2 * STG)

template <bool NFULL>
static __device__ __forceinline__ void mma_loop(
    const __nv_bfloat16* __restrict__ Ah, const __nv_bfloat16* __restrict__ Al,
    const __nv_bfloat16* __restrict__ Bh, const __nv_bfloat16* __restrict__ Bl,
    int m0, int n0, int N, int Kst, int NK, char* smem, float acc[4][4][4]) {
    const uint32_t sb = smem_u32(smem);
    const int tid = threadIdx.x;
    const int lane = tid & 31;
    const int w = tid >> 5;
    const int wm = (w & 1) * 64;
    const int wn = (w >> 1) * 32;
    const int r8  = lane & 7;
    const int oct = lane >> 3;

#define ISSUE(IT) do {                                                        \
        int kt = (IT) << 5;                                                   \
        int bufo = ((IT) & 1) * STG;                                          \
        char* st = smem + bufo;                                               \
        uint32_t stu = sb + bufo;                                             \
        _Pragma("unroll")                                                     \
        for (int i = 0; i < 2; i++) {                                         \
            int idx = tid + (i << 8);                                         \
            int row = idx >> 2, cq = idx & 3;                                 \
            uint32_t off = sw_off(row, cq);                                   \
            size_t ga = (size_t)(m0 + row) * Kst + kt + (cq << 3);            \
            cpa(stu + off, Ah + ga);                                          \
            cpa(stu + 8192 + off, Al + ga);                                   \
            if (NFULL) {                                                      \
                size_t gb = (size_t)(n0 + row) * Kst + kt + (cq << 3);        \
                cpa(stu + 16384 + off, Bh + gb);                              \
                cpa(stu + 24576 + off, Bl + gb);                              \
            } else {                                                          \
                int n = n0 + row;                                             \
                if (n < N) {                                                  \
                    size_t gb = (size_t)n * Kst + kt + (cq << 3);             \
                    cpa(stu + 16384 + off, Bh + gb);                          \
                    cpa(stu + 24576 + off, Bl + gb);                          \
                } else {                                                      \
                    uint4 z4 = make_uint4(0, 0, 0, 0);                        \
                    *(uint4*)(st + 16384 + off) = z4;                         \
                    *(uint4*)(st + 24576 + off) = z4;                         \
                }                                                             \
            }                                                                 \
        }                                                                     \
        asm volatile("cp.async.commit_group;" ::: "memory");                  \
    } while (0)

    ISSUE(0);
    for (int it = 0; it < NK; it++) {
        asm volatile("cp.async.wait_group 0;" ::: "memory");
        __syncthreads();
        if (it + 1 < NK) ISSUE(it + 1);

        const uint32_t base = sb + (it & 1) * STG;
        #pragma unroll
        for (int ks = 0; ks < 2; ks++) {
            uint32_t bH[4][2], bL[4][2], aF[4][4];
            #pragma unroll
            for (int p = 0; p < 2; p++) {
                int n = wn + p * 16 + (oct >> 1) * 8 + r8;
                int kc = ks * 2 + (oct & 1);
                uint32_t ad = base + 16384 + sw_off(n, kc);
                uint32_t t[4];
                ldsm4(t, ad);
                bH[p * 2][0] = t[0]; bH[p * 2][1] = t[1];
                bH[p * 2 + 1][0] = t[2]; bH[p * 2 + 1][1] = t[3];
                ldsm4(t, ad + 8192);
                bL[p * 2][0] = t[0]; bL[p * 2][1] = t[1];
                bL[p * 2 + 1][0] = t[2]; bL[p * 2 + 1][1] = t[3];
            }
            #pragma unroll
            for (int mt = 0; mt < 4; mt++) {
                int row = wm + mt * 16 + (oct & 1) * 8 + r8;
                int kc = ks * 2 + (oct >> 1);
                ldsm4(aF[mt], base + sw_off(row, kc));
            }
            #pragma unroll
            for (int mt = 0; mt < 4; mt++)
                #pragma unroll
                for (int nt = 0; nt < 4; nt++)
                    mma_bf16(acc[mt][nt], aF[mt], bH[nt]);
            #pragma unroll
            for (int mt = 0; mt < 4; mt++)
                #pragma unroll
                for (int nt = 0; nt < 4; nt++)
                    mma_bf16(acc[mt][nt], aF[mt], bL[nt]);
            #pragma unroll
            for (int mt = 0; mt < 4; mt++) {
                int row = wm + mt * 16 + (oct & 1) * 8 + r8;
                int kc = ks * 2 + (oct >> 1);
                ldsm4(aF[mt], base + 8192 + sw_off(row, kc));
            }
            #pragma unroll
            for (int mt = 0; mt < 4; mt++)
                #pragma unroll
                for (int nt = 0; nt < 4; nt++)
                    mma_bf16(acc[mt][nt], aF[mt], bH[nt]);
        }
        __syncthreads();
    }
#undef ISSUE
}

// ---------------- embedding ----------------
__global__ void embed_kernel(const int* __restrict__ ids,
                             const float* __restrict__ tok,
                             const float* __restrict__ pos) {
    int i = blockIdx.x * blockDim.x + threadIdx.x;
    if (i >= NTOK * DM) return;
    int row = i / DM, d = i - row * DM;
    int t = row % TSEQ;
    g_x[i] = tok[(size_t)ids[row] * DM + d] + pos[t * DM + d];
}

// ---------------- fp16 repack: [K,N] fp32 -> [N,K] fp16 hi/lo ----------------
__global__ void __launch_bounds__(256)
repack_t16(const float* __restrict__ src,
           __half* __restrict__ dh, __half* __restrict__ dl, int K, int N) {
    __shared__ float s[64][65];
    size_t mo = (size_t)blockIdx.z * K * N;
    int n0 = blockIdx.x * 64, k0 = blockIdx.y * 64;
    int t = threadIdx.x;
    bool vec = (n0 + 64 <= N) && ((N & 3) == 0);
    #pragma unroll
    for (int p = 0; p < 4; p++) {
        int k = p * 16 + (t >> 4);
        int nl = (t & 15) * 4;
        if (vec) {
            float4 v = *(const float4*)(src + mo + (size_t)(k0 + k) * N + n0 + nl);
            s[nl][k] = v.x; s[nl + 1][k] = v.y; s[nl + 2][k] = v.z; s[nl + 3][k] = v.w;
        } else {
            #pragma unroll
            for (int j = 0; j < 4; j++) {
                int n = n0 + nl + j;
                s[nl + j][k] = (n < N) ? src[mo + (size_t)(k0 + k) * N + n] : 0.f;
            }
        }
    }
    __syncthreads();
    #pragma unroll
    for (int p = 0; p < 2; p++) {
        int nl = p * 32 + (t >> 3);
        int kl = (t & 7) * 8;
        int n = n0 + nl;
        if (n >= N) continue;
        __half hs[8], ls[8];
        #pragma unroll
        for (int j = 0; j < 8; j++) split1h(s[nl][kl + j], hs[j], ls[j]);
        size_t o = mo + (size_t)n * K + k0 + kl;
        *(uint4*)(dh + o) = *(uint4*)hs;
        *(uint4*)(dl + o) = *(uint4*)ls;
    }
}

// ---------------- plain fp16 repack (LM head) ----------------
__global__ void __launch_bounds__(256)
repack_t16p(const float* __restrict__ src, __half* __restrict__ dh, int K, int N) {
    __shared__ float s[64][65];
    int n0 = blockIdx.x * 64, k0 = blockIdx.y * 64;
    int t = threadIdx.x;
    #pragma unroll
    for (int p = 0; p < 4; p++) {
        int k = p * 16 + (t >> 4);
        int nl = (t & 15) * 4;
        #pragma unroll
        for (int j = 0; j < 4; j++) {
            int n = n0 + nl + j;
            s[nl + j][k] = (n < N) ? src[(size_t)(k0 + k) * N + n] : 0.f;
        }
    }
    __syncthreads();
    #pragma unroll
    for (int p = 0; p < 2; p++) {
        int nl = p * 32 + (t >> 3);
        int kl = (t & 7) * 8;
        int n = n0 + nl;
        if (n >= N) continue;
        __half hs[8];
        #pragma unroll
        for (int j = 0; j < 8; j++) hs[j] = __float2half_rn(s[nl][kl + j]);
        *(uint4*)(dh + (size_t)n * K + k0 + kl) = *(uint4*)hs;
    }
}

// qkv: [L,H,D,HD] -> per layer combined [q|k|v][2304, 768] fp16 hi/lo
__global__ void repack_qkv_t(const float* __restrict__ wq,
                             const float* __restrict__ wk,
                             const float* __restrict__ wv) {
    __shared__ float tq[32][33], tk[32][33], tv[32][33];
    int z = blockIdx.z, l = z / NH, h = z % NH;
    int d0 = blockIdx.y * 32, e0 = blockIdx.x * 32;
    int tx = threadIdx.x, ty = threadIdx.y;
    size_t sbo = ((size_t)l * NH + h) * DM * HDIM;
    for (int i = ty; i < 32; i += 8) {
        int d = d0 + i, e = e0 + tx;
        size_t idx = sbo + (size_t)d * HDIM + e;
        tq[i][tx] = wq[idx]; tk[i][tx] = wk[idx]; tv[i][tx] = wv[idx];
    }
    __syncthreads();
    size_t db = (size_t)l * QKVW * DM;
    for (int i = ty; i < 32; i += 8) {
        int e = e0 + i, d = d0 + tx;
        int nq = h * HDIM + e;
        __half hh, ll;
        size_t o;
        o = db + (size_t)nq * DM + d;
        split1h(tq[tx][i], hh, ll); g_tqkv_h[o] = hh; g_tqkv_l[o] = ll;
        o = db + (size_t)(DM + nq) * DM + d;
        split1h(tk[tx][i], hh, ll); g_tqkv_h[o] = hh; g_tqkv_l[o] = ll;
        o = db + (size_t)(2 * DM + nq) * DM + d;
        split1h(tv[tx][i], hh, ll); g_tqkv_h[o] = hh; g_tqkv_l[o] = ll;
    }
}

__global__ void bias_concat(const float* __restrict__ bq,
                            const float* __restrict__ bk,
                            const float* __restrict__ bv) {
    int i = blockIdx.x * blockDim.x + threadIdx.x;
    if (i >= NL * QKVW) return;
    int l = i / QKVW, c = i % QKVW;
    float v = (c < DM) ? bq[l * DM + c]
            : (c < 2 * DM) ? bk[l * DM + c - DM]
            : bv[l * DM + c - 2 * DM];
    g_bqkv[i] = v;
}

// ---------------- layernorm -> plain fp16 ----------------
static __device__ __forceinline__ void ln_stats(const float* x, float& mean,
                                                float& inv) {
    float s = 0.f, s2 = 0.f;
    for (int i = threadIdx.x; i < DM; i += blockDim.x) {
        float v = x[i];
        s += v; s2 += v * v;
    }
    __shared__ float rs[32], rs2[32];
    for (int o = 16; o; o >>= 1) {
        s  += __shfl_down_sync(0xffffffffu, s, o);
        s2 += __shfl_down_sync(0xffffffffu, s2, o);
    }
    int wid = threadIdx.x >> 5, lid = threadIdx.x & 31;
    if (lid == 0) { rs[wid] = s; rs2[wid] = s2; }
    __syncthreads();
    if (wid == 0) {
        int nw = blockDim.x >> 5;
        s  = (lid < nw) ? rs[lid]  : 0.f;
        s2 = (lid < nw) ? rs2[lid] : 0.f;
        for (int o = 16; o; o >>= 1) {
            s  += __shfl_down_sync(0xffffffffu, s, o);
            s2 += __shfl_down_sync(0xffffffffu, s2, o);
        }
        if (lid == 0) { rs[0] = s; rs2[0] = s2; }
    }
    __syncthreads();
    mean = rs[0] * (1.f / DM);
    float var = rs2[0] * (1.f / DM) - mean * mean;
    inv = rsqrtf(var + 1e-5f);
}

__global__ void ln16_kernel(const float* __restrict__ in,
                            __half* __restrict__ o16,
                            const float* __restrict__ g, const float* __restrict__ b) {
    int row = blockIdx.x;
    const float* x = in + (size_t)row * DM;
    float mean, inv;
    ln_stats(x, mean, inv);
    for (int i = threadIdx.x; i < DM; i += blockDim.x) {
        float v = (x[i] - mean) * inv * g[i] + b[i];
        o16[(size_t)row * DM + i] = __float2half_rn(v);
    }
}

// ---------------- fp16 2-pass GEMM, 64x64 tile (full tiles only) ----------------
// mode 0: fp32 C + bias + res; mode 1: fp16 + bias + relu;
// mode 3: fp32 C + bias + res AND fp16 out; mode 4: fp16 + bias.
#define STG64 12288
#define SM_DYN64 (2 * STG64)

__global__ void __launch_bounds__(256, 4)
gemm16_64(const __half* __restrict__ A, const __half* __restrict__ Bh,
          const __half* __restrict__ Bl, float* __restrict__ C,
          __half* __restrict__ C16, int N, int K,
          const float* __restrict__ bias, const float* __restrict__ res, int mode) {
    extern __shared__ char smem[];
    const uint32_t sb = smem_u32(smem);
    const int tid = threadIdx.x;
    const int lane = tid & 31;
    const int w = tid >> 5;
    const int wm = (w & 1) * 32;
    const int wn = (w >> 1) * 16;
    const int r8  = lane & 7;
    const int oct = lane >> 3;
    const int m0 = blockIdx.x * 64;
    const int n0 = blockIdx.y * 64;
    const int NK = K >> 5;
    float acc[2][2][4] = {};

#define ISSUE64(IT) do {                                                      \
        int kt = (IT) << 5;                                                   \
        uint32_t stu = sb + ((IT) & 1) * STG64;                               \
        int row = tid >> 2, cq = tid & 3;                                     \
        uint32_t off = sw_off(row, cq);                                       \
        cpa(stu + off, A + (size_t)(m0 + row) * K + kt + (cq << 3));          \
        size_t gb = (size_t)(n0 + row) * K + kt + (cq << 3);                  \
        cpa(stu + 4096 + off, Bh + gb);                                       \
        cpa(stu + 8192 + off, Bl + gb);                                       \
        asm volatile("cp.async.commit_group;" ::: "memory");                  \
    } while (0)

    ISSUE64(0);
    for (int it = 0; it < NK; it++) {
        asm volatile("cp.async.wait_group 0;" ::: "memory");
        __syncthreads();
        if (it + 1 < NK) ISSUE64(it + 1);

        const uint32_t base = sb + (it & 1) * STG64;
        #pragma unroll
        for (int ks = 0; ks < 2; ks++) {
            uint32_t bH[2][2], bL[2][2], aF[2][4], t[4];
            {
                int n = wn + (oct >> 1) * 8 + r8;
                int kc = ks * 2 + (oct & 1);
                uint32_t ad = base + 4096 + sw_off(n, kc);
                ldsm4(t, ad);
                bH[0][0] = t[0]; bH[0][1] = t[1];
                bH[1][0] = t[2]; bH[1][1] = t[3];
                ldsm4(t, ad + 4096);
                bL[0][0] = t[0]; bL[0][1] = t[1];
                bL[1][0] = t[2]; bL[1][1] = t[3];
            }
            #pragma unroll
            for (int mt = 0; mt < 2; mt++) {
                int row = wm + mt * 16 + (oct & 1) * 8 + r8;
                int kc = ks * 2 + (oct >> 1);
                ldsm4(aF[mt], base + sw_off(row, kc));
            }
            #pragma unroll
            for (int mt = 0; mt < 2; mt++)
                #pragma unroll
                for (int nt = 0; nt < 2; nt++)
                    mma_f16(acc[mt][nt], aF[mt], bH[nt]);
            #pragma unroll
            for (int mt = 0; mt < 2; mt++)
                #pragma unroll
                for (int nt = 0; nt < 2; nt++)
                    mma_f16(acc[mt][nt], aF[mt], bL[nt]);
        }
        __syncthreads();
    }
#undef ISSUE64

    const int g2 = lane >> 2;
    const int t2 = (lane & 3) * 2;
    #pragma unroll
    for (int mt = 0; mt < 2; mt++) {
        #pragma unroll
        for (int nt = 0; nt < 2; nt++) {
            float* c = acc[mt][nt];
            int row = m0 + wm + mt * 16 + g2;
            int col = n0 + wn + nt * 8 + t2;
            float2 bb = *(const float2*)(bias + col);
            float v0 = c[0] + bb.x, v1 = c[1] + bb.y;
            float v2 = c[2] + bb.x, v3 = c[3] + bb.y;
            if (mode == 1) {
                v0 = fmaxf(v0, 0.f); v1 = fmaxf(v1, 0.f);
                v2 = fmaxf(v2, 0.f); v3 = fmaxf(v3, 0.f);
            }
            if (mode == 0 || mode == 3) {
                float2 r0 = *(const float2*)(res + (size_t)row * N + col);
                float2 r1 = *(const float2*)(res + (size_t)(row + 8) * N + col);
                v0 += r0.x; v1 += r0.y; v2 += r1.x; v3 += r1.y;
                *(float2*)(C + (size_t)row * N + col) = make_float2(v0, v1);
                *(float2*)(C + (size_t)(row + 8) * N + col) = make_float2(v2, v3);
            }
            if (mode == 1 || mode == 3 || mode == 4) {
                *(__half2*)(C16 + (size_t)row * N + col) =
                    __halves2half2(__float2half_rn(v0), __float2half_rn(v1));
                *(__half2*)(C16 + (size_t)(row + 8) * N + col) =
                    __halves2half2(__float2half_rn(v2), __float2half_rn(v3));
            }
        }
    }
}

// ---------------- fp16 GEMM, 128x128 tile (qkv scatter + LM head) ----------------
#define STG16 24576
#define SM_DYN16 (2 * STG16)

template <bool TWO>
__global__ void __launch_bounds__(256, 2)
gemm16(const __half* __restrict__ A, const __half* __restrict__ Bh,
       const __half* __restrict__ Bl, float* __restrict__ C,
       int N, int K, const float* __restrict__ bias, int mode) {
    extern __shared__ char smem[];
    const uint32_t sb = smem_u32(smem);
    const int tid = threadIdx.x;
    const int lane = tid & 31;
    const int w = tid >> 5;
    const int wm = (w & 1) * 64;
    const int wn = (w >> 1) * 32;
    const int r8  = lane & 7;
    const int oct = lane >> 3;
    const int m0 = blockIdx.x * GBM;
    const int n0 = blockIdx.y * GBN;
    const int NK = K >> 5;
    float acc[4][4][4] = {};

#define ISSUE16(IT) do {                                                      \
        int kt = (IT) << 5;                                                   \
        int bufo = ((IT) & 1) * STG16;                                        \
        char* st = smem + bufo;                                               \
        uint32_t stu = sb + bufo;                                             \
        _Pragma("unroll")                                                     \
        for (int i = 0; i < 2; i++) {                                         \
            int idx = tid + (i << 8);                                         \
            int row = idx >> 2, cq = idx & 3;                                 \
            uint32_t off = sw_off(row, cq);                                   \
            cpa(stu + off, A + (size_t)(m0 + row) * K + kt + (cq << 3));      \
            int n = n0 + row;                                                 \
            if (n < N) {                                                      \
                size_t gb = (size_t)n * K + kt + (cq << 3);                   \
                cpa(stu + 8192 + off, Bh + gb);                               \
                if (TWO) cpa(stu + 16384 + off, Bl + gb);                     \
            } else {                                                          \
                uint4 z4 = make_uint4(0, 0, 0, 0);                            \
                *(uint4*)(st + 8192 + off) = z4;                              \
                if (TWO) *(uint4*)(st + 16384 + off) = z4;                    \
            }                                                                 \
        }                                                                     \
        asm volatile("cp.async.commit_group;" ::: "memory");                  \
    } while (0)

    ISSUE16(0);
    for (int it = 0; it < NK; it++) {
        asm volatile("cp.async.wait_group 0;" ::: "memory");
        __syncthreads();
        if (it + 1 < NK) ISSUE16(it + 1);

        const uint32_t base = sb + (it & 1) * STG16;
        #pragma unroll
        for (int ks = 0; ks < 2; ks++) {
            uint32_t bH[4][2], bL[4][2], aF[4][4];
            #pragma unroll
            for (int p = 0; p < 2; p++) {
                int n = wn + p * 16 + (oct >> 1) * 8 + r8;
                int kc = ks * 2 + (oct & 1);
                uint32_t ad = base + 8192 + sw_off(n, kc);
                uint32_t t[4];
                ldsm4(t, ad);
                bH[p * 2][0] = t[0]; bH[p * 2][1] = t[1];
                bH[p * 2 + 1][0] = t[2]; bH[p * 2 + 1][1] = t[3];
                if (TWO) {
                    ldsm4(t, ad + 8192);
                    bL[p * 2][0] = t[0]; bL[p * 2][1] = t[1];
                    bL[p * 2 + 1][0] = t[2]; bL[p * 2 + 1][1] = t[3];
                }
            }
            #pragma unroll
            for (int mt = 0; mt < 4; mt++) {
                int row = wm + mt * 16 + (oct & 1) * 8 + r8;
                int kc = ks * 2 + (oct >> 1);
                ldsm4(aF[mt], base + sw_off(row, kc));
            }
            #pragma unroll
            for (int mt = 0; mt < 4; mt++)
                #pragma unroll
                for (int nt = 0; nt < 4; nt++)
                    mma_f16(acc[mt][nt], aF[mt], bH[nt]);
            if (TWO) {
                #pragma unroll
                for (int mt = 0; mt < 4; mt++)
                    #pragma unroll
                    for (int nt = 0; nt < 4; nt++)
                        mma_f16(acc[mt][nt], aF[mt], bL[nt]);
            }
        }
        __syncthreads();
    }
#undef ISSUE16

    const int g2 = lane >> 2;
    const int t2 = (lane & 3) * 2;

    if (mode == 2) {
        // qkv scatter into bf16-split per-head buffers (N == 2304)
        #pragma unroll
        for (int mt = 0; mt < 4; mt++) {
            #pragma unroll
            for (int nt = 0; nt < 4; nt++) {
                float* c = acc[mt][nt];
                int row = m0 + wm + mt * 16 + g2;
                int col = n0 + wn + nt * 8 + t2;
                float2 bb = *(const float2*)(bias + col);
                #pragma unroll
                for (int e = 0; e < 4; e++) {
                    int r = row + (e >> 1) * 8;
                    int cc = col + (e & 1);
                    float v = c[e] + ((e & 1) ? bb.y : bb.x);
                    int b = r >> 9, s = r & 511;
                    int sec = cc / DM, d = cc - sec * DM;
                    int h = d >> 6, ee = d & 63;
                    __nv_bfloat16 hh, ll;
                    split1(v, hh, ll);
                    size_t zo = (size_t)(b * NH + h);
                    if (sec == 0) {
                        size_t o = (zo * TSEQ + s) * HDIM + ee;
                        g_qh[o] = hh; g_ql[o] = ll;
                    } else if (sec == 1) {
                        size_t o = (zo * TSEQ + s) * HDIM + ee;
                        g_kh[o] = hh; g_kl[o] = ll;
                    } else {
                        size_t o = (zo * HDIM + ee) * TSEQ + s;
                        g_vth[o] = hh; g_vtl[o] = ll;
                    }
                }
            }
        }
    } else {
        // fp32 C + bias (LM head; N odd -> scalar guarded)
        #pragma unroll
        for (int mt = 0; mt < 4; mt++) {
            #pragma unroll
            for (int nt = 0; nt < 4; nt++) {
                float* c = acc[mt][nt];
                int row = m0 + wm + mt * 16 + g2;
                int col = n0 + wn + nt * 8 + t2;
                #pragma unroll
                for (int e = 0; e < 2; e++) {
                    int nn = col + e;
                    if (nn < N) {
                        float bb = bias[nn];
                        C[(size_t)row * N + nn] = c[e] + bb;
                        C[(size_t)(row + 8) * N + nn] = c[2 + e] + bb;
                    }
                }
            }
        }
    }
}

// ---------------- attention scores: HMMA, lower-triangular blocks only ----------------
__global__ void __launch_bounds__(256, 2)
attn_sc() {
    extern __shared__ char smem[];
    const int mi_t[10] = {0, 1, 1, 2, 2, 2, 3, 3, 3, 3};
    const int ni_t[10] = {0, 0, 1, 0, 1, 2, 0, 1, 2, 3};
    int z = blockIdx.z;
    int mi = mi_t[blockIdx.x], ni = ni_t[blockIdx.x];
    const __nv_bfloat16* Ah = g_kh + (size_t)z * TSEQ * HDIM;
    const __nv_bfloat16* Al = g_kl + (size_t)z * TSEQ * HDIM;
    const __nv_bfloat16* Bh = g_qh + (size_t)z * TSEQ * HDIM;
    const __nv_bfloat16* Bl = g_ql + (size_t)z * TSEQ * HDIM;
    float acc[4][4][4] = {};
    mma_loop<true>(Ah, Al, Bh, Bl, mi * 128, ni * 128, TSEQ, HDIM, 2, smem, acc);

    const int tid = threadIdx.x;
    const int lane = tid & 31;
    const int w = tid >> 5;
    const int wm = (w & 1) * 64;
    const int wn = (w >> 1) * 32;
    const int g2 = lane >> 2;
    const int t2 = (lane & 3) * 2;
    float* Cs = g_scores + (size_t)z * TSEQ * TSEQ;
    #pragma unroll
    for (int mt = 0; mt < 4; mt++) {
        #pragma unroll
        for (int nt = 0; nt < 4; nt++) {
            float* c = acc[mt][nt];
            int row = mi * 128 + wm + mt * 16 + g2;
            int col = ni * 128 + wn + nt * 8 + t2;
            *(float2*)(Cs + (size_t)row * TSEQ + col) = make_float2(c[0], c[1]);
            *(float2*)(Cs + (size_t)(row + 8) * TSEQ + col) = make_float2(c[2], c[3]);
        }
    }
}

// ---------------- causal softmax: fp32 scores -> split bf16 P ----------------
__global__ void softmax_kernel() {
    int rowg = blockIdx.x;
    int t = rowg & (TSEQ - 1);
    const float* w = g_scores + (size_t)rowg * TSEQ;
    int tid = threadIdx.x;
    bool val0 = (tid <= t), val1 = (tid + 256 <= t);
    float v0 = val0 ? w[tid] : -FLT_MAX;
    float v1 = val1 ? w[tid + 256] : -FLT_MAX;
    __shared__ float sh[256];
    sh[tid] = fmaxf(v0, v1);
    __syncthreads();
    for (int o = 128; o; o >>= 1) {
        if (tid < o) sh[tid] = fmaxf(sh[tid], sh[tid + o]);
        __syncthreads();
    }
    float m = sh[0];
    __syncthreads();
    float e0 = val0 ? expf(v0 - m) : 0.f;
    float e1 = val1 ? expf(v1 - m) : 0.f;
    sh[tid] = e0 + e1;
    __syncthreads();
    for (int o = 128; o; o >>= 1) {
        if (tid < o) sh[tid] += sh[tid + o];
        __syncthreads();
    }
    float inv = 1.f / sh[0];
    size_t ob = (size_t)rowg * TSEQ;
    int lim = ((t >> 7) + 1) << 7;
    __nv_bfloat16 h, l;
    if (tid < lim) {
        split1(e0 * inv, h, l);
        g_ph[ob + tid] = h; g_pl[ob + tid] = l;
    }
    if (tid + 256 < lim) {
        split1(e1 * inv, h, l);
        g_ph[ob + tid + 256] = h; g_pl[ob + tid + 256] = l;
    }
}

// ---------------- attention AV: HMMA, K truncated at diagonal; plain fp16 out ----------------
__global__ void __launch_bounds__(256, 2)
attn_av() {
    extern __shared__ char smem[];
    int z = blockIdx.z, b = z / NH, h = z % NH;
    int mi = blockIdx.x;
    const __nv_bfloat16* Ah = g_ph + (size_t)z * TSEQ * TSEQ;
    const __nv_bfloat16* Al = g_pl + (size_t)z * TSEQ * TSEQ;
    const __nv_bfloat16* Bh = g_vth + (size_t)z * HDIM * TSEQ;
    const __nv_bfloat16* Bl = g_vtl + (size_t)z * HDIM * TSEQ;
    float acc[4][4][4] = {};
    mma_loop<false>(Ah, Al, Bh, Bl, mi * 128, 0, HDIM, TSEQ, (mi + 1) * 4, smem, acc);

    const int tid = threadIdx.x;
    const int lane = tid & 31;
    const int w = tid >> 5;
    const int wm = (w & 1) * 64;
    const int wn = (w >> 1) * 32;
    const int g2 = lane >> 2;
    const int t2 = (lane & 3) * 2;
    if (wn >= HDIM) return;
    #pragma unroll
    for (int mt = 0; mt < 4; mt++) {
        #pragma unroll
        for (int nt = 0; nt < 4; nt++) {
            int col = wn + nt * 8 + t2;
            if (col >= HDIM) continue;
            float* c = acc[mt][nt];
            int t = mi * 128 + wm + mt * 16 + g2;
            size_t o0 = (size_t)(b * TSEQ + t) * DM + h * HDIM + col;
            size_t o1 = (size_t)(b * TSEQ + t + 8) * DM + h * HDIM + col;
            *(__half2*)(g_at16 + o0) =
                __halves2half2(__float2half_rn(c[0]), __float2half_rn(c[1]));
            *(__half2*)(g_at16 + o1) =
                __halves2half2(__float2half_rn(c[2]), __float2half_rn(c[3]));
        }
    }
}

// ---------------- loss ----------------
__global__ void loss_kernel(const float* __restrict__ logits,
                            const int* __restrict__ target) {
    int row = blockIdx.x;
    const float* lg = logits + (size_t)row * VCAB;
    int tid = threadIdx.x;
    float m = -FLT_MAX, s = 0.f;
    for (int i = tid; i < VCAB; i += blockDim.x) {
        float v = lg[i];
        if (v > m) { s = s * expf(m - v) + 1.f; m = v; }
        else       { s += expf(v - m); }
    }
    __shared__ float sm[256], ss[256];
    sm[tid] = m; ss[tid] = s;
    __syncthreads();
    for (int o = 128; o; o >>= 1) {
        if (tid < o) {
            float m2 = sm[tid + o], s2 = ss[tid + o];
            float mm = fmaxf(sm[tid], m2);
            ss[tid] = ss[tid] * expf(sm[tid] - mm) + s2 * expf(m2 - mm);
            sm[tid] = mm;
        }
        __syncthreads();
    }
    if (tid == 0) {
        float lse = sm[0] + logf(ss[0]);
        g_nll[row] = lse - lg[target[row]];
    }
}

__global__ void loss_reduce(float* out) {
    __shared__ float sh[256];
    float s = 0.f;
    for (int i = threadIdx.x; i < NTOK; i += 256) s += g_nll[i];
    sh[threadIdx.x] = s;
    __syncthreads();
    for (int o = 128; o; o >>= 1) {
        if (threadIdx.x < o) sh[threadIdx.x] += sh[threadIdx.x + o];
        __syncthreads();
    }
    if (threadIdx.x == 0) out[0] = sh[0] * (1.f / NTOK);
}

// ---------------- host ----------------
extern "C" void kernel_launch(void* const* d_in, const int* in_sizes, int n_in,
                              void* d_out, int out_size) {
    const int*   x_ids      = (const int*)d_in[0];
    const int*   target     = (const int*)d_in[1];
    const float* tok_emb    = (const float*)d_in[2];
    const float* pos_emb    = (const float*)d_in[3];
    const float* in_proj_w  = (const float*)d_in[4];
    const float* in_proj_b  = (const float*)d_in[5];
    const float* wk         = (const float*)d_in[6];
    const float* bk         = (const float*)d_in[7];
    const float* wq         = (const float*)d_in[8];
    const float* bq         = (const float*)d_in[9];
    const float* wv         = (const float*)d_in[10];
    const float* bv         = (const float*)d_in[11];
    const float* out_proj_w = (const float*)d_in[12];
    const float* out_proj_b = (const float*)d_in[13];
    const float* ff_w1      = (const float*)d_in[14];
    const float* ff_b1      = (const float*)d_in[15];
    const float* ff_w2      = (const float*)d_in[16];
    const float* ff_b2      = (const float*)d_in[17];
    const float* lna_g      = (const float*)d_in[18];
    const float* lna_b      = (const float*)d_in[19];
    const float* lnf_g      = (const float*)d_in[20];
    const float* lnf_b      = (const float*)d_in[21];
    const float* out_w      = (const float*)d_in[22];
    const float* out_b      = (const float*)d_in[23];

    float *px, *plog, *pbqkv;
    cudaGetSymbolAddress((void**)&px,    g_x);
    cudaGetSymbolAddress((void**)&plog,  g_logits_scratch);
    cudaGetSymbolAddress((void**)&pbqkv, g_bqkv);

    __half *ln16, *h2_16, *at16, *ff16, *a16;
    __half *tinh, *tinl, *tqkv_h, *tqkv_l, *top_h, *top_l;
    __half *tf1h, *tf1l, *tf2h, *tf2l, *tw16;
    cudaGetSymbolAddress((void**)&ln16,  g_ln16);
    cudaGetSymbolAddress((void**)&h2_16, g_h2_16);
    cudaGetSymbolAddress((void**)&at16,  g_at16);
    cudaGetSymbolAddress((void**)&ff16,  g_ff16);
    cudaGetSymbolAddress((void**)&a16,   g_a16);
    cudaGetSymbolAddress((void**)&tinh,  g_tin_16h);  cudaGetSymbolAddress((void**)&tinl, g_tin_16l);
    cudaGetSymbolAddress((void**)&tqkv_h, g_tqkv_h);  cudaGetSymbolAddress((void**)&tqkv_l, g_tqkv_l);
    cudaGetSymbolAddress((void**)&top_h, g_top_h);    cudaGetSymbolAddress((void**)&top_l, g_top_l);
    cudaGetSymbolAddress((void**)&tf1h,  g_tf1_16h);  cudaGetSymbolAddress((void**)&tf1l, g_tf1_16l);
    cudaGetSymbolAddress((void**)&tf2h,  g_tf2_16h);  cudaGetSymbolAddress((void**)&tf2l, g_tf2_16l);
    cudaGetSymbolAddress((void**)&tw16,  g_tw16);

    cudaFuncSetAttribute(attn_sc,   cudaFuncAttributeMaxDynamicSharedMemorySize, SM_DYN);
    cudaFuncSetAttribute(attn_av,   cudaFuncAttributeMaxDynamicSharedMemorySize, SM_DYN);
    cudaFuncSetAttribute(gemm16_64, cudaFuncAttributeMaxDynamicSharedMemorySize, SM_DYN64);
    cudaFuncSetAttribute(gemm16<true>,  cudaFuncAttributeMaxDynamicSharedMemorySize, SM_DYN16);
    cudaFuncSetAttribute(gemm16<false>, cudaFuncAttributeMaxDynamicSharedMemorySize, SM_DYN16);

    const size_t LOGITS_N = (size_t)NTOK * VCAB;
    float* logits = ((size_t)out_size >= LOGITS_N) ? (float*)d_out : plog;

    dim3 tb(32, 8);
    dim3 blk(256);
    dim3 g64_dm(NTOK / 64, DM / 64);        // (32, 12) = 384
    dim3 g64_ff1(NTOK / 64, DFF / 64);      // (32, 48) = 1536
    dim3 g_qkvg(NTOK / GBM, QKVW / GBN);    // (16, 18) = 288
    dim3 g_lm(NTOK / GBM, (VCAB + GBN - 1) / GBN);
    dim3 g_sc(10, 1, NZ);
    dim3 g_av(TSEQ / GBM, 1, NZ);

    embed_kernel<<<(NTOK * DM + 255) / 256, 256>>>(x_ids, tok_emb, pos_emb);   // 0
    repack_t16<<<dim3(12, 12, NL), blk>>>(in_proj_w, tinh, tinl, DM, DM);      // 1
    ln16_kernel<<<NTOK, 256>>>(px, ln16, lna_g, lna_b);                        // 2
    gemm16_64<<<g64_dm, blk, SM_DYN64>>>(ln16, tinh, tinl,                     // 3 <- profiled
                                         nullptr, h2_16, DM, DM,
                                         in_proj_b, nullptr, 4);
    repack_qkv_t<<<dim3(2, 24, NL * NH), tb>>>(wq, wk, wv);
    bias_concat<<<(NL * QKVW + 255) / 256, 256>>>(bq, bk, bv);
    repack_t16<<<dim3(12, 12, NL), blk>>>(out_proj_w, top_h, top_l, DM, DM);
    repack_t16<<<dim3(48, 12, NL), blk>>>(ff_w1, tf1h, tf1l, DM, DFF);
    repack_t16<<<dim3(12, 48, NL), blk>>>(ff_w2, tf2h, tf2l, DFF, DM);
    repack_t16p<<<dim3((VCAB + 63) / 64, 12, 1), blk>>>(out_w, tw16, DM, VCAB);

    for (int l = 0; l < NL; l++) {
        size_t wd = (size_t)l * DM * DM;
        size_t wqk = (size_t)l * QKVW * DM;
        size_t wf = (size_t)l * DM * DFF;
        if (l > 0) {
            ln16_kernel<<<NTOK, 256>>>(px, ln16, lna_g + l * DM, lna_b + l * DM);
            gemm16_64<<<g64_dm, blk, SM_DYN64>>>(ln16, tinh + wd, tinl + wd,
                                                 nullptr, h2_16, DM, DM,
                                                 in_proj_b + l * DM, nullptr, 4);
        }
        gemm16<true><<<g_qkvg, blk, SM_DYN16>>>(h2_16, tqkv_h + wqk, tqkv_l + wqk,
                                                nullptr, QKVW, DM,
                                                pbqkv + l * QKVW, 2);
        attn_sc<<<g_sc, blk, SM_DYN>>>();
        softmax_kernel<<<NZ * TSEQ, 256>>>();
        attn_av<<<g_av, blk, SM_DYN>>>();
        gemm16_64<<<g64_dm, blk, SM_DYN64>>>(at16, top_h + wd, top_l + wd,
                                             px, nullptr, DM, DM,
                                             out_proj_b + l * DM, px, 0);
        ln16_kernel<<<NTOK, 256>>>(px, ln16, lnf_g + l * DM, lnf_b + l * DM);
        gemm16_64<<<g64_ff1, blk, SM_DYN64>>>(ln16, tf1h + wf, tf1l + wf,
                                              nullptr, ff16, DFF, DM,
                                              ff_b1 + l * DFF, nullptr, 1);
        int m2 = (l == NL - 1) ? 3 : 0;
        gemm16_64<<<g64_dm, blk, SM_DYN64>>>(ff16, tf2h + wf, tf2l + wf,
                                             px, a16, DM, DFF,
                                             ff_b2 + l * DM, px, m2);
    }

    // LM head: plain fp16 1-pass
    gemm16<false><<<g_lm, blk, SM_DYN16>>>(a16, tw16, nullptr, logits,
                                           VCAB, DM, out_b, 0);

    if ((size_t)out_size != LOGITS_N) {
        loss_kernel<<<NTOK, 256>>>(logits, target);
        loss_reduce<<<1, 256>>>((float*)d_out + (out_size - 1));
    }
}

// round 15
// speedup vs baseline: 1.4147x; 1.4147x over previous
#include <cuda_runtime.h>
#include <cuda_bf16.h>
#include <cuda_fp16.h>
#include <math.h>
#include <float.h>
#include <stdint.h>

// ---------------- model constants ----------------
#define VCAB 50257
#define DM   768
#define NL   6
#define NH   12
#define HDIM 64
#define BBAT 4
#define TSEQ 512
#define NTOK (BBAT * TSEQ)     // 2048
#define DFF  (4 * DM)          // 3072
#define QKVW (3 * DM)          // 2304
#define NZ   (BBAT * NH)       // 48

// ---------------- scratch ----------------
__device__ float g_x[NTOK * DM];
__device__ float g_scores[(size_t)NZ * TSEQ * TSEQ];
__device__ float g_nll[NTOK];
__device__ float g_logits_scratch[(size_t)NTOK * VCAB];

// attention operands (bf16 split, unchanged precision)
__device__ __nv_bfloat16 g_qh[NZ * TSEQ * HDIM], g_ql[NZ * TSEQ * HDIM];
__device__ __nv_bfloat16 g_kh[NZ * TSEQ * HDIM], g_kl[NZ * TSEQ * HDIM];
__device__ __nv_bfloat16 g_vth[NZ * HDIM * TSEQ], g_vtl[NZ * HDIM * TSEQ];
__device__ __nv_bfloat16 g_ph[(size_t)NZ * TSEQ * TSEQ], g_pl[(size_t)NZ * TSEQ * TSEQ];

__device__ float g_bqkv[NL * QKVW];

// fp16 activations
__device__ __half g_ln16[NTOK * DM];      // LN out (attn & ff, reused sequentially)
__device__ __half g_h2_16[NTOK * DM];     // in_proj out -> qkv in
__device__ __half g_at16[NTOK * DM];      // attention out -> out_proj in
__device__ __half g_ff16[NTOK * DFF];
__device__ __half g_a16[NTOK * DM];       // LM-head in

// fp16 hi/lo weights
__device__ __half g_tin_16h[NL * DM * DM], g_tin_16l[NL * DM * DM];
__device__ __half g_tqkv_h[(size_t)NL * QKVW * DM], g_tqkv_l[(size_t)NL * QKVW * DM];
__device__ __half g_top_h[NL * DM * DM], g_top_l[NL * DM * DM];
__device__ __half g_tf1_16h[(size_t)NL * DM * DFF], g_tf1_16l[(size_t)NL * DM * DFF];
__device__ __half g_tf2_16h[(size_t)NL * DM * DFF], g_tf2_16l[(size_t)NL * DM * DFF];
__device__ __half g_tw16[(size_t)VCAB * DM];

// ---------------- helpers ----------------
static __device__ __forceinline__ uint32_t smem_u32(const void* p) {
    uint32_t a;
    asm("{ .reg .u64 t; cvta.to.shared.u64 t, %1; cvt.u32.u64 %0, t; }"
        : "=r"(a) : "l"(p));
    return a;
}
static __device__ __forceinline__ void ldsm4(uint32_t* r, uint32_t addr) {
    asm volatile("ldmatrix.sync.aligned.m8n8.x4.shared.b16 {%0,%1,%2,%3}, [%4];"
                 : "=r"(r[0]), "=r"(r[1]), "=r"(r[2]), "=r"(r[3]) : "r"(addr));
}
static __device__ __forceinline__ void mma_bf16(float* c, const uint32_t* a,
                                                const uint32_t* b) {
    asm volatile(
        "mma.sync.aligned.m16n8k16.row.col.f32.bf16.bf16.f32 "
        "{%0,%1,%2,%3}, {%4,%5,%6,%7}, {%8,%9}, {%0,%1,%2,%3};"
        : "+f"(c[0]), "+f"(c[1]), "+f"(c[2]), "+f"(c[3])
        : "r"(a[0]), "r"(a[1]), "r"(a[2]), "r"(a[3]), "r"(b[0]), "r"(b[1]));
}
static __device__ __forceinline__ void mma_f16(float* c, const uint32_t* a,
                                               const uint32_t* b) {
    asm volatile(
        "mma.sync.aligned.m16n8k16.row.col.f32.f16.f16.f32 "
        "{%0,%1,%2,%3}, {%4,%5,%6,%7}, {%8,%9}, {%0,%1,%2,%3};"
        : "+f"(c[0]), "+f"(c[1]), "+f"(c[2]), "+f"(c[3])
        : "r"(a[0]), "r"(a[1]), "r"(a[2]), "r"(a[3]), "r"(b[0]), "r"(b[1]));
}
static __device__ __forceinline__ void cpa(uint32_t dst, const void* src) {
    asm volatile("cp.async.cg.shared.global [%0], [%1], 16;" :: "r"(dst), "l"(src));
}
static __device__ __forceinline__ uint32_t sw_off(int row, int kchunk) {
    return (uint32_t)(row * 64 + ((kchunk ^ ((row >> 1) & 3)) << 4));
}
static __device__ __forceinline__ void split1(float v, __nv_bfloat16& h,
                                              __nv_bfloat16& l) {
    h = __float2bfloat16(v);
    l = __float2bfloat16(v - __bfloat162float(h));
}
static __device__ __forceinline__ void split1h(float v, __half& h, __half& l) {
    h = __float2half_rn(v);
    l = __float2half_rn(v - __half2float(h));
}

// ---------------- bf16 3-pass HMMA mainloop (attention only) ----------------
#define GBM 128
#define GBN 128
#define STG 32768
#define SM_DYN (2 * STG)

template <bool NFULL>
static __device__ __forceinline__ void mma_loop(
    const __nv_bfloat16* __restrict__ Ah, const __nv_bfloat16* __restrict__ Al,
    const __nv_bfloat16* __restrict__ Bh, const __nv_bfloat16* __restrict__ Bl,
    int m0, int n0, int N, int Kst, int NK, char* smem, float acc[4][4][4]) {
    const uint32_t sb = smem_u32(smem);
    const int tid = threadIdx.x;
    const int lane = tid & 31;
    const int w = tid >> 5;
    const int wm = (w & 1) * 64;
    const int wn = (w >> 1) * 32;
    const int r8  = lane & 7;
    const int oct = lane >> 3;

#define ISSUE(IT) do {                                                        \
        int kt = (IT) << 5;                                                   \
        int bufo = ((IT) & 1) * STG;                                          \
        char* st = smem + bufo;                                               \
        uint32_t stu = sb + bufo;                                             \
        _Pragma("unroll")                                                     \
        for (int i = 0; i < 2; i++) {                                         \
            int idx = tid + (i << 8);                                         \
            int row = idx >> 2, cq = idx & 3;                                 \
            uint32_t off = sw_off(row, cq);                                   \
            size_t ga = (size_t)(m0 + row) * Kst + kt + (cq << 3);            \
            cpa(stu + off, Ah + ga);                                          \
            cpa(stu + 8192 + off, Al + ga);                                   \
            if (NFULL) {                                                      \
                size_t gb = (size_t)(n0 + row) * Kst + kt + (cq << 3);        \
                cpa(stu + 16384 + off, Bh + gb);                              \
                cpa(stu + 24576 + off, Bl + gb);                              \
            } else {                                                          \
                int n = n0 + row;                                             \
                if (n < N) {                                                  \
                    size_t gb = (size_t)n * Kst + kt + (cq << 3);             \
                    cpa(stu + 16384 + off, Bh + gb);                          \
                    cpa(stu + 24576 + off, Bl + gb);                          \
                } else {                                                      \
                    uint4 z4 = make_uint4(0, 0, 0, 0);                        \
                    *(uint4*)(st + 16384 + off) = z4;                         \
                    *(uint4*)(st + 24576 + off) = z4;                         \
                }                                                             \
            }                                                                 \
        }                                                                     \
        asm volatile("cp.async.commit_group;" ::: "memory");                  \
    } while (0)

    ISSUE(0);
    for (int it = 0; it < NK; it++) {
        asm volatile("cp.async.wait_group 0;" ::: "memory");
        __syncthreads();
        if (it + 1 < NK) ISSUE(it + 1);

        const uint32_t base = sb + (it & 1) * STG;
        #pragma unroll
        for (int ks = 0; ks < 2; ks++) {
            uint32_t bH[4][2], bL[4][2], aF[4][4];
            #pragma unroll
            for (int p = 0; p < 2; p++) {
                int n = wn + p * 16 + (oct >> 1) * 8 + r8;
                int kc = ks * 2 + (oct & 1);
                uint32_t ad = base + 16384 + sw_off(n, kc);
                uint32_t t[4];
                ldsm4(t, ad);
                bH[p * 2][0] = t[0]; bH[p * 2][1] = t[1];
                bH[p * 2 + 1][0] = t[2]; bH[p * 2 + 1][1] = t[3];
                ldsm4(t, ad + 8192);
                bL[p * 2][0] = t[0]; bL[p * 2][1] = t[1];
                bL[p * 2 + 1][0] = t[2]; bL[p * 2 + 1][1] = t[3];
            }
            #pragma unroll
            for (int mt = 0; mt < 4; mt++) {
                int row = wm + mt * 16 + (oct & 1) * 8 + r8;
                int kc = ks * 2 + (oct >> 1);
                ldsm4(aF[mt], base + sw_off(row, kc));
            }
            #pragma unroll
            for (int mt = 0; mt < 4; mt++)
                #pragma unroll
                for (int nt = 0; nt < 4; nt++)
                    mma_bf16(acc[mt][nt], aF[mt], bH[nt]);
            #pragma unroll
            for (int mt = 0; mt < 4; mt++)
                #pragma unroll
                for (int nt = 0; nt < 4; nt++)
                    mma_bf16(acc[mt][nt], aF[mt], bL[nt]);
            #pragma unroll
            for (int mt = 0; mt < 4; mt++) {
                int row = wm + mt * 16 + (oct & 1) * 8 + r8;
                int kc = ks * 2 + (oct >> 1);
                ldsm4(aF[mt], base + 8192 + sw_off(row, kc));
            }
            #pragma unroll
            for (int mt = 0; mt < 4; mt++)
                #pragma unroll
                for (int nt = 0; nt < 4; nt++)
                    mma_bf16(acc[mt][nt], aF[mt], bH[nt]);
        }
        __syncthreads();
    }
#undef ISSUE
}

// ---------------- embedding ----------------
__global__ void embed_kernel(const int* __restrict__ ids,
                             const float* __restrict__ tok,
                             const float* __restrict__ pos) {
    int i = blockIdx.x * blockDim.x + threadIdx.x;
    if (i >= NTOK * DM) return;
    int row = i / DM, d = i - row * DM;
    int t = row % TSEQ;
    g_x[i] = tok[(size_t)ids[row] * DM + d] + pos[t * DM + d];
}

// ---------------- fp16 repack: [K,N] fp32 -> [N,K] fp16 hi/lo ----------------
__global__ void __launch_bounds__(256)
repack_t16(const float* __restrict__ src,
           __half* __restrict__ dh, __half* __restrict__ dl, int K, int N) {
    __shared__ float s[64][65];
    size_t mo = (size_t)blockIdx.z * K * N;
    int n0 = blockIdx.x * 64, k0 = blockIdx.y * 64;
    int t = threadIdx.x;
    bool vec = (n0 + 64 <= N) && ((N & 3) == 0);
    #pragma unroll
    for (int p = 0; p < 4; p++) {
        int k = p * 16 + (t >> 4);
        int nl = (t & 15) * 4;
        if (vec) {
            float4 v = *(const float4*)(src + mo + (size_t)(k0 + k) * N + n0 + nl);
            s[nl][k] = v.x; s[nl + 1][k] = v.y; s[nl + 2][k] = v.z; s[nl + 3][k] = v.w;
        } else {
            #pragma unroll
            for (int j = 0; j < 4; j++) {
                int n = n0 + nl + j;
                s[nl + j][k] = (n < N) ? src[mo + (size_t)(k0 + k) * N + n] : 0.f;
            }
        }
    }
    __syncthreads();
    #pragma unroll
    for (int p = 0; p < 2; p++) {
        int nl = p * 32 + (t >> 3);
        int kl = (t & 7) * 8;
        int n = n0 + nl;
        if (n >= N) continue;
        __half hs[8], ls[8];
        #pragma unroll
        for (int j = 0; j < 8; j++) split1h(s[nl][kl + j], hs[j], ls[j]);
        size_t o = mo + (size_t)n * K + k0 + kl;
        *(uint4*)(dh + o) = *(uint4*)hs;
        *(uint4*)(dl + o) = *(uint4*)ls;
    }
}

// ---------------- plain fp16 repack (LM head) ----------------
__global__ void __launch_bounds__(256)
repack_t16p(const float* __restrict__ src, __half* __restrict__ dh, int K, int N) {
    __shared__ float s[64][65];
    int n0 = blockIdx.x * 64, k0 = blockIdx.y * 64;
    int t = threadIdx.x;
    #pragma unroll
    for (int p = 0; p < 4; p++) {
        int k = p * 16 + (t >> 4);
        int nl = (t & 15) * 4;
        #pragma unroll
        for (int j = 0; j < 4; j++) {
            int n = n0 + nl + j;
            s[nl + j][k] = (n < N) ? src[(size_t)(k0 + k) * N + n] : 0.f;
        }
    }
    __syncthreads();
    #pragma unroll
    for (int p = 0; p < 2; p++) {
        int nl = p * 32 + (t >> 3);
        int kl = (t & 7) * 8;
        int n = n0 + nl;
        if (n >= N) continue;
        __half hs[8];
        #pragma unroll
        for (int j = 0; j < 8; j++) hs[j] = __float2half_rn(s[nl][kl + j]);
        *(uint4*)(dh + (size_t)n * K + k0 + kl) = *(uint4*)hs;
    }
}

// qkv: [L,H,D,HD] -> per layer combined [q|k|v][2304, 768] fp16 hi/lo
__global__ void repack_qkv_t(const float* __restrict__ wq,
                             const float* __restrict__ wk,
                             const float* __restrict__ wv) {
    __shared__ float tq[32][33], tk[32][33], tv[32][33];
    int z = blockIdx.z, l = z / NH, h = z % NH;
    int d0 = blockIdx.y * 32, e0 = blockIdx.x * 32;
    int tx = threadIdx.x, ty = threadIdx.y;
    size_t sbo = ((size_t)l * NH + h) * DM * HDIM;
    for (int i = ty; i < 32; i += 8) {
        int d = d0 + i, e = e0 + tx;
        size_t idx = sbo + (size_t)d * HDIM + e;
        tq[i][tx] = wq[idx]; tk[i][tx] = wk[idx]; tv[i][tx] = wv[idx];
    }
    __syncthreads();
    size_t db = (size_t)l * QKVW * DM;
    for (int i = ty; i < 32; i += 8) {
        int e = e0 + i, d = d0 + tx;
        int nq = h * HDIM + e;
        __half hh, ll;
        size_t o;
        o = db + (size_t)nq * DM + d;
        split1h(tq[tx][i], hh, ll); g_tqkv_h[o] = hh; g_tqkv_l[o] = ll;
        o = db + (size_t)(DM + nq) * DM + d;
        split1h(tk[tx][i], hh, ll); g_tqkv_h[o] = hh; g_tqkv_l[o] = ll;
        o = db + (size_t)(2 * DM + nq) * DM + d;
        split1h(tv[tx][i], hh, ll); g_tqkv_h[o] = hh; g_tqkv_l[o] = ll;
    }
}

__global__ void bias_concat(const float* __restrict__ bq,
                            const float* __restrict__ bk,
                            const float* __restrict__ bv) {
    int i = blockIdx.x * blockDim.x + threadIdx.x;
    if (i >= NL * QKVW) return;
    int l = i / QKVW, c = i % QKVW;
    float v = (c < DM) ? bq[l * DM + c]
            : (c < 2 * DM) ? bk[l * DM + c - DM]
            : bv[l * DM + c - 2 * DM];
    g_bqkv[i] = v;
}

// ---------------- layernorm -> plain fp16 ----------------
static __device__ __forceinline__ void ln_stats(const float* x, float& mean,
                                                float& inv) {
    float s = 0.f, s2 = 0.f;
    for (int i = threadIdx.x; i < DM; i += blockDim.x) {
        float v = x[i];
        s += v; s2 += v * v;
    }
    __shared__ float rs[32], rs2[32];
    for (int o = 16; o; o >>= 1) {
        s  += __shfl_down_sync(0xffffffffu, s, o);
        s2 += __shfl_down_sync(0xffffffffu, s2, o);
    }
    int wid = threadIdx.x >> 5, lid = threadIdx.x & 31;
    if (lid == 0) { rs[wid] = s; rs2[wid] = s2; }
    __syncthreads();
    if (wid == 0) {
        int nw = blockDim.x >> 5;
        s  = (lid < nw) ? rs[lid]  : 0.f;
        s2 = (lid < nw) ? rs2[lid] : 0.f;
        for (int o = 16; o; o >>= 1) {
            s  += __shfl_down_sync(0xffffffffu, s, o);
            s2 += __shfl_down_sync(0xffffffffu, s2, o);
        }
        if (lid == 0) { rs[0] = s; rs2[0] = s2; }
    }
    __syncthreads();
    mean = rs[0] * (1.f / DM);
    float var = rs2[0] * (1.f / DM) - mean * mean;
    inv = rsqrtf(var + 1e-5f);
}

__global__ void ln16_kernel(const float* __restrict__ in,
                            __half* __restrict__ o16,
                            const float* __restrict__ g, const float* __restrict__ b) {
    int row = blockIdx.x;
    const float* x = in + (size_t)row * DM;
    float mean, inv;
    ln_stats(x, mean, inv);
    for (int i = threadIdx.x; i < DM; i += blockDim.x) {
        float v = (x[i] - mean) * inv * g[i] + b[i];
        o16[(size_t)row * DM + i] = __float2half_rn(v);
    }
}

// ---------------- fp16 GEMM, 128x128 tile (A plain fp16; B hi/lo if TWO) ----------------
// mode 0: fp32 C + bias (+res);  mode 1: fp16 + bias + relu;
// mode 2: qkv scatter; mode 3: fp32 + bias + res AND fp16; mode 4: fp16 + bias.
#define STG16 24576
#define SM_DYN16 (2 * STG16)

template <bool TWO>
__global__ void __launch_bounds__(256, 2)
gemm16(const __half* __restrict__ A, const __half* __restrict__ Bh,
       const __half* __restrict__ Bl, float* __restrict__ C,
       __half* __restrict__ C16, int N, int K,
       const float* __restrict__ bias, const float* __restrict__ res, int mode) {
    extern __shared__ char smem[];
    const uint32_t sb = smem_u32(smem);
    const int tid = threadIdx.x;
    const int lane = tid & 31;
    const int w = tid >> 5;
    const int wm = (w & 1) * 64;
    const int wn = (w >> 1) * 32;
    const int r8  = lane & 7;
    const int oct = lane >> 3;
    const int m0 = blockIdx.x * GBM;
    const int n0 = blockIdx.y * GBN;
    const int NK = K >> 5;
    float acc[4][4][4] = {};

#define ISSUE16(IT) do {                                                      \
        int kt = (IT) << 5;                                                   \
        int bufo = ((IT) & 1) * STG16;                                        \
        char* st = smem + bufo;                                               \
        uint32_t stu = sb + bufo;                                             \
        _Pragma("unroll")                                                     \
        for (int i = 0; i < 2; i++) {                                         \
            int idx = tid + (i << 8);                                         \
            int row = idx >> 2, cq = idx & 3;                                 \
            uint32_t off = sw_off(row, cq);                                   \
            cpa(stu + off, A + (size_t)(m0 + row) * K + kt + (cq << 3));      \
            int n = n0 + row;                                                 \
            if (n < N) {                                                      \
                size_t gb = (size_t)n * K + kt + (cq << 3);                   \
                cpa(stu + 8192 + off, Bh + gb);                               \
                if (TWO) cpa(stu + 16384 + off, Bl + gb);                     \
            } else {                                                          \
                uint4 z4 = make_uint4(0, 0, 0, 0);                            \
                *(uint4*)(st + 8192 + off) = z4;                              \
                if (TWO) *(uint4*)(st + 16384 + off) = z4;                    \
            }                                                                 \
        }                                                                     \
        asm volatile("cp.async.commit_group;" ::: "memory");                  \
    } while (0)

    ISSUE16(0);
    for (int it = 0; it < NK; it++) {
        asm volatile("cp.async.wait_group 0;" ::: "memory");
        __syncthreads();
        if (it + 1 < NK) ISSUE16(it + 1);

        const uint32_t base = sb + (it & 1) * STG16;
        #pragma unroll
        for (int ks = 0; ks < 2; ks++) {
            uint32_t bH[4][2], bL[4][2], aF[4][4];
            #pragma unroll
            for (int p = 0; p < 2; p++) {
                int n = wn + p * 16 + (oct >> 1) * 8 + r8;
                int kc = ks * 2 + (oct & 1);
                uint32_t ad = base + 8192 + sw_off(n, kc);
                uint32_t t[4];
                ldsm4(t, ad);
                bH[p * 2][0] = t[0]; bH[p * 2][1] = t[1];
                bH[p * 2 + 1][0] = t[2]; bH[p * 2 + 1][1] = t[3];
                if (TWO) {
                    ldsm4(t, ad + 8192);
                    bL[p * 2][0] = t[0]; bL[p * 2][1] = t[1];
                    bL[p * 2 + 1][0] = t[2]; bL[p * 2 + 1][1] = t[3];
                }
            }
            #pragma unroll
            for (int mt = 0; mt < 4; mt++) {
                int row = wm + mt * 16 + (oct & 1) * 8 + r8;
                int kc = ks * 2 + (oct >> 1);
                ldsm4(aF[mt], base + sw_off(row, kc));
            }
            #pragma unroll
            for (int mt = 0; mt < 4; mt++)
                #pragma unroll
                for (int nt = 0; nt < 4; nt++)
                    mma_f16(acc[mt][nt], aF[mt], bH[nt]);
            if (TWO) {
                #pragma unroll
                for (int mt = 0; mt < 4; mt++)
                    #pragma unroll
                    for (int nt = 0; nt < 4; nt++)
                        mma_f16(acc[mt][nt], aF[mt], bL[nt]);
            }
        }
        __syncthreads();
    }
#undef ISSUE16

    const int g2 = lane >> 2;
    const int t2 = (lane & 3) * 2;
    const bool fast = (n0 + GBN <= N) && ((N & 1) == 0);

    #pragma unroll
    for (int mt = 0; mt < 4; mt++) {
        #pragma unroll
        for (int nt = 0; nt < 4; nt++) {
            float* c = acc[mt][nt];
            int row = m0 + wm + mt * 16 + g2;
            int col = n0 + wn + nt * 8 + t2;
            if (mode == 1 || mode == 4) {
                // fp16 out + bias (+relu if mode 1); full tiles only
                float2 bb = *(const float2*)(bias + col);
                float v0 = c[0] + bb.x, v1 = c[1] + bb.y;
                float v2 = c[2] + bb.x, v3 = c[3] + bb.y;
                if (mode == 1) {
                    v0 = fmaxf(v0, 0.f); v1 = fmaxf(v1, 0.f);
                    v2 = fmaxf(v2, 0.f); v3 = fmaxf(v3, 0.f);
                }
                *(__half2*)(C16 + (size_t)row * N + col) =
                    __halves2half2(__float2half_rn(v0), __float2half_rn(v1));
                *(__half2*)(C16 + (size_t)(row + 8) * N + col) =
                    __halves2half2(__float2half_rn(v2), __float2half_rn(v3));
            } else if (mode == 2) {
                // qkv scatter into bf16-split per-head buffers (N == 2304)
                float2 bb = *(const float2*)(bias + col);
                #pragma unroll
                for (int e = 0; e < 4; e++) {
                    int r = row + (e >> 1) * 8;
                    int cc = col + (e & 1);
                    float v = c[e] + ((e & 1) ? bb.y : bb.x);
                    int b = r >> 9, s = r & 511;
                    int sec = cc / DM, d = cc - sec * DM;
                    int h = d >> 6, ee = d & 63;
                    __nv_bfloat16 hh, ll;
                    split1(v, hh, ll);
                    size_t zo = (size_t)(b * NH + h);
                    if (sec == 0) {
                        size_t o = (zo * TSEQ + s) * HDIM + ee;
                        g_qh[o] = hh; g_ql[o] = ll;
                    } else if (sec == 1) {
                        size_t o = (zo * TSEQ + s) * HDIM + ee;
                        g_kh[o] = hh; g_kl[o] = ll;
                    } else {
                        size_t o = (zo * HDIM + ee) * TSEQ + s;
                        g_vth[o] = hh; g_vtl[o] = ll;
                    }
                }
            } else if (fast) {
                float2 v0 = make_float2(c[0], c[1]);
                float2 v1 = make_float2(c[2], c[3]);
                if (bias) {
                    float2 bb = *(const float2*)(bias + col);
                    v0.x += bb.x; v0.y += bb.y; v1.x += bb.x; v1.y += bb.y;
                }
                if (res) {
                    float2 r0 = *(const float2*)(res + (size_t)row * N + col);
                    float2 r1 = *(const float2*)(res + (size_t)(row + 8) * N + col);
                    v0.x += r0.x; v0.y += r0.y; v1.x += r1.x; v1.y += r1.y;
                }
                *(float2*)(C + (size_t)row * N + col) = v0;
                *(float2*)(C + (size_t)(row + 8) * N + col) = v1;
                if (mode == 3) {
                    *(__half2*)(C16 + (size_t)row * N + col) =
                        __halves2half2(__float2half_rn(v0.x), __float2half_rn(v0.y));
                    *(__half2*)(C16 + (size_t)(row + 8) * N + col) =
                        __halves2half2(__float2half_rn(v1.x), __float2half_rn(v1.y));
                }
            } else {
                #pragma unroll
                for (int e = 0; e < 2; e++) {
                    int nn = col + e;
                    if (nn < N) {
                        float v0 = c[e], v1 = c[2 + e];
                        if (bias) { float bb = bias[nn]; v0 += bb; v1 += bb; }
                        if (res) {
                            v0 += res[(size_t)row * N + nn];
                            v1 += res[(size_t)(row + 8) * N + nn];
                        }
                        C[(size_t)row * N + nn] = v0;
                        C[(size_t)(row + 8) * N + nn] = v1;
                    }
                }
            }
        }
    }
}

// ---------------- attention scores: HMMA, lower-triangular blocks only ----------------
__global__ void __launch_bounds__(256, 2)
attn_sc() {
    extern __shared__ char smem[];
    const int mi_t[10] = {0, 1, 1, 2, 2, 2, 3, 3, 3, 3};
    const int ni_t[10] = {0, 0, 1, 0, 1, 2, 0, 1, 2, 3};
    int z = blockIdx.z;
    int mi = mi_t[blockIdx.x], ni = ni_t[blockIdx.x];
    const __nv_bfloat16* Ah = g_kh + (size_t)z * TSEQ * HDIM;
    const __nv_bfloat16* Al = g_kl + (size_t)z * TSEQ * HDIM;
    const __nv_bfloat16* Bh = g_qh + (size_t)z * TSEQ * HDIM;
    const __nv_bfloat16* Bl = g_ql + (size_t)z * TSEQ * HDIM;
    float acc[4][4][4] = {};
    mma_loop<true>(Ah, Al, Bh, Bl, mi * 128, ni * 128, TSEQ, HDIM, 2, smem, acc);

    const int tid = threadIdx.x;
    const int lane = tid & 31;
    const int w = tid >> 5;
    const int wm = (w & 1) * 64;
    const int wn = (w >> 1) * 32;
    const int g2 = lane >> 2;
    const int t2 = (lane & 3) * 2;
    float* Cs = g_scores + (size_t)z * TSEQ * TSEQ;
    #pragma unroll
    for (int mt = 0; mt < 4; mt++) {
        #pragma unroll
        for (int nt = 0; nt < 4; nt++) {
            float* c = acc[mt][nt];
            int row = mi * 128 + wm + mt * 16 + g2;
            int col = ni * 128 + wn + nt * 8 + t2;
            *(float2*)(Cs + (size_t)row * TSEQ + col) = make_float2(c[0], c[1]);
            *(float2*)(Cs + (size_t)(row + 8) * TSEQ + col) = make_float2(c[2], c[3]);
        }
    }
}

// ---------------- causal softmax: fp32 scores -> split bf16 P ----------------
__global__ void softmax_kernel() {
    int rowg = blockIdx.x;
    int t = rowg & (TSEQ - 1);
    const float* w = g_scores + (size_t)rowg * TSEQ;
    int tid = threadIdx.x;
    bool val0 = (tid <= t), val1 = (tid + 256 <= t);
    float v0 = val0 ? w[tid] : -FLT_MAX;
    float v1 = val1 ? w[tid + 256] : -FLT_MAX;
    __shared__ float sh[256];
    sh[tid] = fmaxf(v0, v1);
    __syncthreads();
    for (int o = 128; o; o >>= 1) {
        if (tid < o) sh[tid] = fmaxf(sh[tid], sh[tid + o]);
        __syncthreads();
    }
    float m = sh[0];
    __syncthreads();
    float e0 = val0 ? expf(v0 - m) : 0.f;
    float e1 = val1 ? expf(v1 - m) : 0.f;
    sh[tid] = e0 + e1;
    __syncthreads();
    for (int o = 128; o; o >>= 1) {
        if (tid < o) sh[tid] += sh[tid + o];
        __syncthreads();
    }
    float inv = 1.f / sh[0];
    size_t ob = (size_t)rowg * TSEQ;
    int lim = ((t >> 7) + 1) << 7;
    __nv_bfloat16 h, l;
    if (tid < lim) {
        split1(e0 * inv, h, l);
        g_ph[ob + tid] = h; g_pl[ob + tid] = l;
    }
    if (tid + 256 < lim) {
        split1(e1 * inv, h, l);
        g_ph[ob + tid + 256] = h; g_pl[ob + tid + 256] = l;
    }
}

// ---------------- attention AV: HMMA, K truncated at diagonal; plain fp16 out ----------------
__global__ void __launch_bounds__(256, 2)
attn_av() {
    extern __shared__ char smem[];
    int z = blockIdx.z, b = z / NH, h = z % NH;
    int mi = blockIdx.x;
    const __nv_bfloat16* Ah = g_ph + (size_t)z * TSEQ * TSEQ;
    const __nv_bfloat16* Al = g_pl + (size_t)z * TSEQ * TSEQ;
    const __nv_bfloat16* Bh = g_vth + (size_t)z * HDIM * TSEQ;
    const __nv_bfloat16* Bl = g_vtl + (size_t)z * HDIM * TSEQ;
    float acc[4][4][4] = {};
    mma_loop<false>(Ah, Al, Bh, Bl, mi * 128, 0, HDIM, TSEQ, (mi + 1) * 4, smem, acc);

    const int tid = threadIdx.x;
    const int lane = tid & 31;
    const int w = tid >> 5;
    const int wm = (w & 1) * 64;
    const int wn = (w >> 1) * 32;
    const int g2 = lane >> 2;
    const int t2 = (lane & 3) * 2;
    if (wn >= HDIM) return;
    #pragma unroll
    for (int mt = 0; mt < 4; mt++) {
        #pragma unroll
        for (int nt = 0; nt < 4; nt++) {
            int col = wn + nt * 8 + t2;
            if (col >= HDIM) continue;
            float* c = acc[mt][nt];
            int t = mi * 128 + wm + mt * 16 + g2;
            size_t o0 = (size_t)(b * TSEQ + t) * DM + h * HDIM + col;
            size_t o1 = (size_t)(b * TSEQ + t + 8) * DM + h * HDIM + col;
            *(__half2*)(g_at16 + o0) =
                __halves2half2(__float2half_rn(c[0]), __float2half_rn(c[1]));
            *(__half2*)(g_at16 + o1) =
                __halves2half2(__float2half_rn(c[2]), __float2half_rn(c[3]));
        }
    }
}

// ---------------- loss ----------------
__global__ void loss_kernel(const float* __restrict__ logits,
                            const int* __restrict__ target) {
    int row = blockIdx.x;
    const float* lg = logits + (size_t)row * VCAB;
    int tid = threadIdx.x;
    float m = -FLT_MAX, s = 0.f;
    for (int i = tid; i < VCAB; i += blockDim.x) {
        float v = lg[i];
        if (v > m) { s = s * expf(m - v) + 1.f; m = v; }
        else       { s += expf(v - m); }
    }
    __shared__ float sm[256], ss[256];
    sm[tid] = m; ss[tid] = s;
    __syncthreads();
    for (int o = 128; o; o >>= 1) {
        if (tid < o) {
            float m2 = sm[tid + o], s2 = ss[tid + o];
            float mm = fmaxf(sm[tid], m2);
            ss[tid] = ss[tid] * expf(sm[tid] - mm) + s2 * expf(m2 - mm);
            sm[tid] = mm;
        }
        __syncthreads();
    }
    if (tid == 0) {
        float lse = sm[0] + logf(ss[0]);
        g_nll[row] = lse - lg[target[row]];
    }
}

__global__ void loss_reduce(float* out) {
    __shared__ float sh[256];
    float s = 0.f;
    for (int i = threadIdx.x; i < NTOK; i += 256) s += g_nll[i];
    sh[threadIdx.x] = s;
    __syncthreads();
    for (int o = 128; o; o >>= 1) {
        if (threadIdx.x < o) sh[threadIdx.x] += sh[threadIdx.x + o];
        __syncthreads();
    }
    if (threadIdx.x == 0) out[0] = sh[0] * (1.f / NTOK);
}

// ---------------- host ----------------
extern "C" void kernel_launch(void* const* d_in, const int* in_sizes, int n_in,
                              void* d_out, int out_size) {
    const int*   x_ids      = (const int*)d_in[0];
    const int*   target     = (const int*)d_in[1];
    const float* tok_emb    = (const float*)d_in[2];
    const float* pos_emb    = (const float*)d_in[3];
    const float* in_proj_w  = (const float*)d_in[4];
    const float* in_proj_b  = (const float*)d_in[5];
    const float* wk         = (const float*)d_in[6];
    const float* bk         = (const float*)d_in[7];
    const float* wq         = (const float*)d_in[8];
    const float* bq         = (const float*)d_in[9];
    const float* wv         = (const float*)d_in[10];
    const float* bv         = (const float*)d_in[11];
    const float* out_proj_w = (const float*)d_in[12];
    const float* out_proj_b = (const float*)d_in[13];
    const float* ff_w1      = (const float*)d_in[14];
    const float* ff_b1      = (const float*)d_in[15];
    const float* ff_w2      = (const float*)d_in[16];
    const float* ff_b2      = (const float*)d_in[17];
    const float* lna_g      = (const float*)d_in[18];
    const float* lna_b      = (const float*)d_in[19];
    const float* lnf_g      = (const float*)d_in[20];
    const float* lnf_b      = (const float*)d_in[21];
    const float* out_w      = (const float*)d_in[22];
    const float* out_b      = (const float*)d_in[23];

    float *px, *plog, *pbqkv;
    cudaGetSymbolAddress((void**)&px,    g_x);
    cudaGetSymbolAddress((void**)&plog,  g_logits_scratch);
    cudaGetSymbolAddress((void**)&pbqkv, g_bqkv);

    __half *ln16, *h2_16, *at16, *ff16, *a16;
    __half *tinh, *tinl, *tqkv_h, *tqkv_l, *top_h, *top_l;
    __half *tf1h, *tf1l, *tf2h, *tf2l, *tw16;
    cudaGetSymbolAddress((void**)&ln16,  g_ln16);
    cudaGetSymbolAddress((void**)&h2_16, g_h2_16);
    cudaGetSymbolAddress((void**)&at16,  g_at16);
    cudaGetSymbolAddress((void**)&ff16,  g_ff16);
    cudaGetSymbolAddress((void**)&a16,   g_a16);
    cudaGetSymbolAddress((void**)&tinh,  g_tin_16h);  cudaGetSymbolAddress((void**)&tinl, g_tin_16l);
    cudaGetSymbolAddress((void**)&tqkv_h, g_tqkv_h);  cudaGetSymbolAddress((void**)&tqkv_l, g_tqkv_l);
    cudaGetSymbolAddress((void**)&top_h, g_top_h);    cudaGetSymbolAddress((void**)&top_l, g_top_l);
    cudaGetSymbolAddress((void**)&tf1h,  g_tf1_16h);  cudaGetSymbolAddress((void**)&tf1l, g_tf1_16l);
    cudaGetSymbolAddress((void**)&tf2h,  g_tf2_16h);  cudaGetSymbolAddress((void**)&tf2l, g_tf2_16l);
    cudaGetSymbolAddress((void**)&tw16,  g_tw16);

    cudaFuncSetAttribute(attn_sc,  cudaFuncAttributeMaxDynamicSharedMemorySize, SM_DYN);
    cudaFuncSetAttribute(attn_av,  cudaFuncAttributeMaxDynamicSharedMemorySize, SM_DYN);
    cudaFuncSetAttribute(gemm16<true>,  cudaFuncAttributeMaxDynamicSharedMemorySize, SM_DYN16);
    cudaFuncSetAttribute(gemm16<false>, cudaFuncAttributeMaxDynamicSharedMemorySize, SM_DYN16);

    const size_t LOGITS_N = (size_t)NTOK * VCAB;
    float* logits = ((size_t)out_size >= LOGITS_N) ? (float*)d_out : plog;

    dim3 tb(32, 8);
    dim3 blk(256);
    dim3 g_dm(NTOK / GBM, DM / GBN);        // (16, 6)
    dim3 g_qkvg(NTOK / GBM, QKVW / GBN);    // (16, 18)
    dim3 g_ff1(NTOK / GBM, DFF / GBN);      // (16, 24)
    dim3 g_lm(NTOK / GBM, (VCAB + GBN - 1) / GBN);
    dim3 g_sc(10, 1, NZ);
    dim3 g_av(TSEQ / GBM, 1, NZ);

    embed_kernel<<<(NTOK * DM + 255) / 256, 256>>>(x_ids, tok_emb, pos_emb);   // 0
    repack_t16<<<dim3(12, 12, NL), blk>>>(in_proj_w, tinh, tinl, DM, DM);      // 1
    ln16_kernel<<<NTOK, 256>>>(px, ln16, lna_g, lna_b);                        // 2
    gemm16<true><<<g_dm, blk, SM_DYN16>>>(ln16, tinh, tinl,                    // 3 <- profiled
                                          nullptr, h2_16, DM, DM,
                                          in_proj_b, nullptr, 4);
    repack_qkv_t<<<dim3(2, 24, NL * NH), tb>>>(wq, wk, wv);
    bias_concat<<<(NL * QKVW + 255) / 256, 256>>>(bq, bk, bv);
    repack_t16<<<dim3(12, 12, NL), blk>>>(out_proj_w, top_h, top_l, DM, DM);
    repack_t16<<<dim3(48, 12, NL), blk>>>(ff_w1, tf1h, tf1l, DM, DFF);
    repack_t16<<<dim3(12, 48, NL), blk>>>(ff_w2, tf2h, tf2l, DFF, DM);
    repack_t16p<<<dim3((VCAB + 63) / 64, 12, 1), blk>>>(out_w, tw16, DM, VCAB);

    for (int l = 0; l < NL; l++) {
        size_t wd = (size_t)l * DM * DM;
        size_t wqk = (size_t)l * QKVW * DM;
        size_t wf = (size_t)l * DM * DFF;
        if (l > 0) {
            ln16_kernel<<<NTOK, 256>>>(px, ln16, lna_g + l * DM, lna_b + l * DM);
            gemm16<true><<<g_dm, blk, SM_DYN16>>>(ln16, tinh + wd, tinl + wd,
                                                  nullptr, h2_16, DM, DM,
                                                  in_proj_b + l * DM, nullptr, 4);
        }
        gemm16<true><<<g_qkvg, blk, SM_DYN16>>>(h2_16, tqkv_h + wqk, tqkv_l + wqk,
                                                nullptr, nullptr, QKVW, DM,
                                                pbqkv + l * QKVW, nullptr, 2);
        attn_sc<<<g_sc, blk, SM_DYN>>>();
        softmax_kernel<<<NZ * TSEQ, 256>>>();
        attn_av<<<g_av, blk, SM_DYN>>>();
        gemm16<true><<<g_dm, blk, SM_DYN16>>>(at16, top_h + wd, top_l + wd,
                                              px, nullptr, DM, DM,
                                              out_proj_b + l * DM, px, 0);
        ln16_kernel<<<NTOK, 256>>>(px, ln16, lnf_g + l * DM, lnf_b + l * DM);
        gemm16<true><<<g_ff1, blk, SM_DYN16>>>(ln16, tf1h + wf, tf1l + wf,
                                               nullptr, ff16, DFF, DM,
                                               ff_b1 + l * DFF, nullptr, 1);
        int m2 = (l == NL - 1) ? 3 : 0;
        gemm16<true><<<g_dm, blk, SM_DYN16>>>(ff16, tf2h + wf, tf2l + wf,
                                              px, a16, DM, DFF,
                                              ff_b2 + l * DM, px, m2);
    }

    // LM head: plain fp16 1-pass
    gemm16<false><<<g_lm, blk, SM_DYN16>>>(a16, tw16, nullptr, logits, nullptr,
                                           VCAB, DM, out_b, nullptr, 0);

    if ((size_t)out_size != LOGITS_N) {
        loss_kernel<<<NTOK, 256>>>(logits, target);
        loss_reduce<<<1, 256>>>((float*)d_out + (out_size - 1));
    }
}